// round 2
// baseline (speedup 1.0000x reference)
#include <cuda_runtime.h>
#include <cstdint>

#define B 8
#define C 128
#define H 256
#define W 256
#define HW (H*W)        // 65536
#define HW4 (HW/4)      // 16384

// scratch: pooled max map and attention map, [B, H, W]
__device__ float g_pooled[B * HW];
__device__ float g_attn[B * HW];

// ---------------------------------------------------------------------------
// Kernel 1 (per batch): pooled[b,h,w] = max_c x[b,c,h,w]
// 4-way channel split: block = 64 float4-pixels x 4 channel groups (256 thr).
// 256 blocks per batch. smem reduce across groups.
// ---------------------------------------------------------------------------
__global__ void pool_max_b_kernel(const float* __restrict__ x, int b) {
    __shared__ float4 red[256];
    const int tid = threadIdx.x;
    const int grp = tid >> 6;          // 0..3  (channel group)
    const int pix = tid & 63;          // 0..63 (float4 pixel within block)
    const int hw4 = blockIdx.x * 64 + pix;

    const float4* p = reinterpret_cast<const float4*>(x)
                      + ((size_t)b * C + (size_t)grp * 32) * HW4 + hw4;

    float4 m = p[0];
    #pragma unroll 8
    for (int c = 1; c < 32; ++c) {
        float4 v = p[(size_t)c * HW4];
        m.x = fmaxf(m.x, v.x);
        m.y = fmaxf(m.y, v.y);
        m.z = fmaxf(m.z, v.z);
        m.w = fmaxf(m.w, v.w);
    }
    red[tid] = m;
    __syncthreads();

    if (grp == 0) {
        float4 a = red[pix];
        float4 b1 = red[64 + pix];
        float4 c1 = red[128 + pix];
        float4 d1 = red[192 + pix];
        a.x = fmaxf(fmaxf(a.x, b1.x), fmaxf(c1.x, d1.x));
        a.y = fmaxf(fmaxf(a.y, b1.y), fmaxf(c1.y, d1.y));
        a.z = fmaxf(fmaxf(a.z, b1.z), fmaxf(c1.z, d1.z));
        a.w = fmaxf(fmaxf(a.w, b1.w), fmaxf(c1.w, d1.w));
        reinterpret_cast<float4*>(g_pooled)[(size_t)b * HW4 + hw4] = a;
    }
}

// ---------------------------------------------------------------------------
// Kernel 2 (per batch): attn = sigmoid(conv7x7(pooled) + bias), zero pad 3.
// Tile 64x16 outputs per block, 256 threads, smem halo tile 70x22.
// ---------------------------------------------------------------------------
#define TW 64
#define TH 16

__global__ void conv_sigmoid_b_kernel(const float* __restrict__ cw,
                                      const float* __restrict__ cb, int b) {
    __shared__ float s[TH + 6][TW + 6];
    const int tx0 = blockIdx.x * TW;
    const int ty0 = blockIdx.y * TH;
    const float* pb = g_pooled + b * HW;

    for (int i = threadIdx.x; i < (TH + 6) * (TW + 6); i += blockDim.x) {
        int ly = i / (TW + 6);
        int lx = i - ly * (TW + 6);
        int gy = ty0 + ly - 3;
        int gx = tx0 + lx - 3;
        float v = 0.0f;
        if (gy >= 0 && gy < H && gx >= 0 && gx < W) v = pb[gy * W + gx];
        s[ly][lx] = v;
    }
    __syncthreads();

    float wr[49];
    #pragma unroll
    for (int i = 0; i < 49; ++i) wr[i] = __ldg(&cw[i]);
    const float bias = __ldg(&cb[0]);

    const int lx  = threadIdx.x & (TW - 1);
    const int ly0 = threadIdx.x >> 6;        // 0..3

    #pragma unroll
    for (int r = 0; r < TH; r += 4) {
        const int ly = ly0 + r;
        float acc = bias;
        #pragma unroll
        for (int i = 0; i < 7; ++i)
            #pragma unroll
            for (int j = 0; j < 7; ++j)
                acc = fmaf(s[ly + i][lx + j], wr[i * 7 + j], acc);
        float sg = 1.0f / (1.0f + __expf(-acc));
        g_attn[b * HW + (ty0 + ly) * W + tx0 + lx] = sg;
    }
}

// ---------------------------------------------------------------------------
// Kernel 3 (per batch): out = x * attn.  x_b should be L2-resident from the
// pool pass (33.5MB x + 33.5MB out < 126MB L2).
// ---------------------------------------------------------------------------
__global__ void mul_b_kernel(const float* __restrict__ x,
                             float* __restrict__ out, int b) {
    size_t i = (size_t)blockIdx.x * blockDim.x + threadIdx.x;  // float4 idx within batch
    int hw4 = (int)(i & (HW4 - 1));
    size_t gi = (size_t)b * C * HW4 + i;
    float4 a = reinterpret_cast<const float4*>(g_attn)[(size_t)b * HW4 + hw4];
    float4 v = reinterpret_cast<const float4*>(x)[gi];
    v.x *= a.x; v.y *= a.y; v.z *= a.z; v.w *= a.w;
    reinterpret_cast<float4*>(out)[gi] = v;
}

// ---------------------------------------------------------------------------
extern "C" void kernel_launch(void* const* d_in, const int* in_sizes, int n_in,
                              void* d_out, int out_size) {
    const float* x  = (const float*)d_in[0];
    const float* cw = (const float*)d_in[1];   // [1,1,7,7]
    const float* cb = (const float*)d_in[2];   // [1]
    float* out = (float*)d_out;

    dim3 g2(W / TW, H / TH, 1);
    for (int b = 0; b < B; ++b) {
        // pool: 256 blocks (64 float4-pixels x 4 channel groups each)
        pool_max_b_kernel<<<HW4 / 64, 256>>>(x, b);
        // conv+sigmoid on 256x256 map
        conv_sigmoid_b_kernel<<<g2, 256>>>(cw, cb, b);
        // multiply: C*HW4 = 2,097,152 float4 / 256 = 8192 blocks
        mul_b_kernel<<<(C * HW4) / 256, 256>>>(x, out, b);
    }
}